// round 13
// baseline (speedup 1.0000x reference)
#include <cuda_runtime.h>
#include <math.h>

#define NN 131072          // nodes
#define EE 2097152         // edges
#define BB 64              // graphs
#define NPG 2048
#define KTOP 30
#define FULLMASK 0xffffffffu

// fast tanh: 1 - 2/(e^{2x}+1).  rel-err ~1e-6, inside the 1e-3 budget.
__device__ __forceinline__ float ftanh(float x) {
    float e = __expf(2.0f * x);
    return 1.0f - __fdividef(2.0f, e + 1.0f);
}

// ---------------- scratch (static device globals; no allocation) ----------------
__device__ int   g_rowstart[NN];
__device__ int   g_cursor[NN];
__device__ int   g_blocksums[128];
__device__ int2  g_csr[EE];        // .x = col, .y = eid
__device__ float g_e2n[NN * 32];
__device__ float g_z[NN * 32];
__device__ float g_z2[NN * 32];
__device__ float g_h0[NN * 32];
__device__ float g_h1[NN * 32];
__device__ float g_h2[NN * 32];
__device__ float g_z3[NN];
__device__ float g_h3[NN];
__device__ int   g_topk[BB * KTOP];

// ---------------- CSR build: prefix scan of degrees (2 kernels) ----------------
__global__ void k_scanA(const float* __restrict__ degs) {
    __shared__ int tmp[1024];
    int t = threadIdx.x;
    int idx = blockIdx.x * 1024 + t;
    int c = (int)(degs[idx] + 0.5f) - 1;             // node_degs = count + 1
    tmp[t] = c;
    __syncthreads();
    for (int off = 1; off < 1024; off <<= 1) {
        int v = (t >= off) ? tmp[t - off] : 0;
        __syncthreads();
        tmp[t] += v;
        __syncthreads();
    }
    g_rowstart[idx] = tmp[t] - c;                    // exclusive within block
    if (t == 1023) g_blocksums[blockIdx.x] = tmp[t];
}

__global__ void k_scanB() {
    __shared__ int bs[128];
    int t = threadIdx.x;
    if (t < 128) bs[t] = g_blocksums[t];
    __syncthreads();
    int off = 0;
    for (int i = 0; i < blockIdx.x; i++) off += bs[i];
    int idx = blockIdx.x * 1024 + t;
    int v = g_rowstart[idx] + off;
    g_rowstart[idx] = v;
    g_cursor[idx]   = v;
}

__global__ void k_fill(const int* __restrict__ erow, const int* __restrict__ ecol) {
    int e = blockIdx.x * 256 + threadIdx.x;
    int r = erow[e];
    int p = atomicAdd(&g_cursor[r], 1);
    g_csr[p] = make_int2(ecol[e], e);
}

// ---------------- e2n: dedicated gather kernel (full occupancy, max MLP) ------
// warp per node; random 128B edgef lines, 8 loads in flight per warp.
// Launch index 3 -> profiled by ncu.
__global__ void k_e2n(const float* __restrict__ edgef, const float* __restrict__ degs) {
    int t = threadIdx.x;
    int wid = t >> 5, lane = t & 31;
    int v = blockIdx.x * 8 + wid;
    int cnt = (int)(degs[v] + 0.5f) - 1;
    int start = g_rowstart[v];

    float a0 = 0.f, a1 = 0.f, a2 = 0.f, a3 = 0.f;
    float a4 = 0.f, a5 = 0.f, a6 = 0.f, a7 = 0.f;
    for (int kb = 0; kb < cnt; kb += 32) {
        int m = min(32, cnt - kb);
        int eid = (lane < m) ? g_csr[start + kb + lane].y : 0;
        int k = 0;
        for (; k + 8 <= m; k += 8) {
            int e0 = __shfl_sync(FULLMASK, eid, k);
            int e1 = __shfl_sync(FULLMASK, eid, k + 1);
            int e2 = __shfl_sync(FULLMASK, eid, k + 2);
            int e3 = __shfl_sync(FULLMASK, eid, k + 3);
            int e4 = __shfl_sync(FULLMASK, eid, k + 4);
            int e5 = __shfl_sync(FULLMASK, eid, k + 5);
            int e6 = __shfl_sync(FULLMASK, eid, k + 6);
            int e7 = __shfl_sync(FULLMASK, eid, k + 7);
            a0 += edgef[e0 * 32 + lane];
            a1 += edgef[e1 * 32 + lane];
            a2 += edgef[e2 * 32 + lane];
            a3 += edgef[e3 * 32 + lane];
            a4 += edgef[e4 * 32 + lane];
            a5 += edgef[e5 * 32 + lane];
            a6 += edgef[e6 * 32 + lane];
            a7 += edgef[e7 * 32 + lane];
        }
        for (; k < m; k++) {
            int e0 = __shfl_sync(FULLMASK, eid, k);
            a0 += edgef[e0 * 32 + lane];
        }
    }
    g_e2n[v * 32 + lane] = ((a0 + a1) + (a2 + a3)) + ((a4 + a5) + (a6 + a7));
}

// ---------------- z0 GEMM: z = W0 @ [nf | e2n], register-tiled ----------------
__global__ void k_z0g(const float* __restrict__ nodef, const float* __restrict__ W0) {
    __shared__ float sWt[32 * 164];                  // [c][i], row pad 164
    int t = threadIdx.x;
    int wid = t >> 5, lane = t & 31;
    int nbase = blockIdx.x * 64;

    for (int s = t; s < 32 * 160; s += 256) {
        int c = s / 160, i = s % 160;
        sWt[c * 164 + i] = W0[c * 160 + i];
    }
    __syncthreads();

    float acc[8];
#pragma unroll
    for (int n = 0; n < 8; n++) acc[n] = 0.f;
    int n0 = wid * 8;
    const float4* nf4 = reinterpret_cast<const float4*>(nodef + (nbase + n0) * 128);
    const float4* e24 = reinterpret_cast<const float4*>(g_e2n + (nbase + n0) * 32);

    for (int i4 = 0; i4 < 32; i4++) {                 // nf part: i = 0..127
        float4 wv = *reinterpret_cast<const float4*>(&sWt[lane * 164 + i4 * 4]);
#pragma unroll
        for (int n = 0; n < 8; n++) {
            float4 hv = __ldg(&nf4[n * 32 + i4]);     // warp-uniform broadcast
            acc[n] += wv.x * hv.x + wv.y * hv.y + wv.z * hv.z + wv.w * hv.w;
        }
    }
#pragma unroll
    for (int i4 = 0; i4 < 8; i4++) {                  // e2n part: i = 128..159
        float4 wv = *reinterpret_cast<const float4*>(&sWt[lane * 164 + 128 + i4 * 4]);
#pragma unroll
        for (int n = 0; n < 8; n++) {
            float4 hv = __ldg(&e24[n * 8 + i4]);      // warp-uniform broadcast
            acc[n] += wv.x * hv.x + wv.y * hv.y + wv.z * hv.z + wv.w * hv.w;
        }
    }
#pragma unroll
    for (int n = 0; n < 8; n++)
        g_z[(nbase + n0 + n) * 32 + lane] = acc[n];
}

// ---------------- GNN layer: register-tiled --------------
// Block = 64 nodes, 8 warps.  Phase A: warp-per-node gather + tanh -> smem.
// Phase B: z_next = Wn @ h, warp = 8 nodes x 32 ch, LDS.128 weights (pad 36).
template <int STAGE>
__global__ void k_layer(const float* __restrict__ bias, const float* __restrict__ degs,
                        const float* __restrict__ Wn) {
    const float* zin  = (STAGE == 1) ? g_z2 : g_z;
    float* hout = (STAGE == 0) ? g_h0 : (STAGE == 1) ? g_h1 : g_h2;

    __shared__ float sWt[32 * 36];                   // [c][j], pad 36 (=4 mod 32)
    __shared__ float sh[64 * 32];                    // h tile
    int t = threadIdx.x;
    int wid = t >> 5, lane = t & 31;
    int nbase = blockIdx.x * 64;

    if (STAGE < 2) {
        for (int s = t; s < 1024; s += 256) {
            int c = s >> 5, j = s & 31;
            sWt[c * 36 + j] = Wn[c * 32 + j];
        }
    }
    float bl = bias[lane];

    // Phase A: gather pooled, tanh, stash h
    for (int rep = 0; rep < 8; rep++) {
        int nloc = rep * 8 + wid;
        int v = nbase + nloc;
        float deg = degs[v];
        int cnt = (int)(deg + 0.5f) - 1;
        int start = g_rowstart[v];

        float p0 = zin[v * 32 + lane], p1 = 0.f, p2 = 0.f, p3 = 0.f;
        float p4 = 0.f, p5 = 0.f, p6 = 0.f, p7 = 0.f;
        for (int kb = 0; kb < cnt; kb += 32) {
            int m = min(32, cnt - kb);
            int col = (lane < m) ? g_csr[start + kb + lane].x : 0;
            int k = 0;
            for (; k + 8 <= m; k += 8) {
                int c0 = __shfl_sync(FULLMASK, col, k);
                int c1 = __shfl_sync(FULLMASK, col, k + 1);
                int c2 = __shfl_sync(FULLMASK, col, k + 2);
                int c3 = __shfl_sync(FULLMASK, col, k + 3);
                int c4 = __shfl_sync(FULLMASK, col, k + 4);
                int c5 = __shfl_sync(FULLMASK, col, k + 5);
                int c6 = __shfl_sync(FULLMASK, col, k + 6);
                int c7 = __shfl_sync(FULLMASK, col, k + 7);
                p0 += zin[c0 * 32 + lane];
                p1 += zin[c1 * 32 + lane];
                p2 += zin[c2 * 32 + lane];
                p3 += zin[c3 * 32 + lane];
                p4 += zin[c4 * 32 + lane];
                p5 += zin[c5 * 32 + lane];
                p6 += zin[c6 * 32 + lane];
                p7 += zin[c7 * 32 + lane];
            }
            for (; k < m; k++) {
                int cx = __shfl_sync(FULLMASK, col, k);
                p0 += zin[cx * 32 + lane];
            }
        }
        float p = ((p0 + p1) + (p2 + p3)) + ((p4 + p5) + (p6 + p7));
        float h = ftanh(__fdividef(p + bl, deg));
        sh[nloc * 32 + lane] = h;
        hout[v * 32 + lane] = h;
    }
    __syncthreads();

    // Phase B: projection
    int n0 = wid * 8;
    if (STAGE < 2) {
        float acc[8];
#pragma unroll
        for (int n = 0; n < 8; n++) acc[n] = 0.f;
#pragma unroll
        for (int i4 = 0; i4 < 8; i4++) {
            float4 wv = *reinterpret_cast<const float4*>(&sWt[lane * 36 + i4 * 4]);
#pragma unroll
            for (int n = 0; n < 8; n++) {
                float4 hv = *reinterpret_cast<const float4*>(&sh[(n0 + n) * 32 + i4 * 4]);
                acc[n] += wv.x * hv.x + wv.y * hv.y + wv.z * hv.z + wv.w * hv.w;
            }
        }
        float* zout = (STAGE == 0) ? g_z2 : g_z;
#pragma unroll
        for (int n = 0; n < 8; n++)
            zout[(nbase + n0 + n) * 32 + lane] = acc[n];
    } else {
        float w3 = Wn[lane];                          // 1x32, L2/const cached
#pragma unroll
        for (int n = 0; n < 8; n++) {
            float part = w3 * sh[(n0 + n) * 32 + lane];
#pragma unroll
            for (int o = 16; o; o >>= 1) part += __shfl_xor_sync(FULLMASK, part, o);
            if (lane == 0) g_z3[nbase + n0 + n] = part;
        }
    }
}

// ---------------- layer 3 (scalar channel) ----------------
__global__ void k_layer3(const float* __restrict__ degs, const float* __restrict__ b3) {
    int t = threadIdx.x;
    int warp = (blockIdx.x * 256 + t) >> 5;
    int lane = t & 31;
    int v = warp;
    float deg = degs[v];
    int cnt = (int)(deg + 0.5f) - 1;
    int start = g_rowstart[v];
    float s = 0.f;
    for (int k = lane; k < cnt; k += 32) s += g_z3[g_csr[start + k].x];
#pragma unroll
    for (int o = 16; o; o >>= 1) s += __shfl_xor_sync(FULLMASK, s, o);
    if (lane == 0) {
        float pooled = s + g_z3[v];
        g_h3[v] = ftanh(__fdividef(pooled + b3[0], deg));
    }
}

// ---------------- sortpool: top-K per graph by h3, JAX tie semantics ----------------
__global__ void k_topk() {
    int b = blockIdx.x;
    int t = threadIdx.x;                       // 256 threads
    __shared__ float sv[NPG];
    __shared__ float rv[256];
    __shared__ int   ri[256];
    for (int i = t; i < NPG; i += 256) sv[i] = g_h3[b * NPG + i];
    __syncthreads();
    for (int r = 0; r < KTOP; r++) {
        float bv = -3.0f;
        int bi = NPG;
        for (int i = t; i < NPG; i += 256) {
            float v = sv[i];
            if (v > bv || (v == bv && i < bi)) { bv = v; bi = i; }
        }
        rv[t] = bv; ri[t] = bi;
        __syncthreads();
        for (int o = 128; o > 0; o >>= 1) {
            if (t < o) {
                float v2 = rv[t + o]; int i2 = ri[t + o];
                if (v2 > rv[t] || (v2 == rv[t] && i2 < ri[t])) { rv[t] = v2; ri[t] = i2; }
            }
            __syncthreads();
        }
        if (t == 0) { g_topk[b * KTOP + r] = ri[0]; sv[ri[0]] = -2.0f; }
        __syncthreads();
    }
}

// ---------------- CNN head + MLP + log_softmax, one block per graph ----------------
__global__ void k_classify(const float* __restrict__ Wc1, const float* __restrict__ bc1,
                           const float* __restrict__ Wc2, const float* __restrict__ bc2,
                           const float* __restrict__ Wh,  const float* __restrict__ bh,
                           const float* __restrict__ Wo,  const float* __restrict__ bo,
                           float* __restrict__ out) {
    int b = blockIdx.x, t = threadIdx.x;       // 128 threads
    __shared__ float pg[KTOP * 97];
    __shared__ float y[16 * 30];
    __shared__ float mp[16 * 15];
    __shared__ float dd[352];
    __shared__ float hh[128];
    __shared__ float lg[10];
    __shared__ float lse;

    for (int s = t; s < KTOP * 97; s += 128) {
        int k = s / 97, d = s % 97;
        int node = g_topk[b * KTOP + k] + b * NPG;
        float v;
        if (d < 32)      v = g_h0[node * 32 + d];
        else if (d < 64) v = g_h1[node * 32 + (d - 32)];
        else if (d < 96) v = g_h2[node * 32 + (d - 64)];
        else             v = g_h3[node];
        pg[k * 97 + d] = v;
    }
    __syncthreads();
    for (int s = t; s < 480; s += 128) {
        int c = s / 30, k = s % 30;
        float acc = bc1[c];
        for (int d = 0; d < 97; d++) acc += Wc1[c * 97 + d] * pg[k * 97 + d];
        y[c * 30 + k] = fmaxf(acc, 0.f);
    }
    __syncthreads();
    for (int s = t; s < 240; s += 128) {
        int c = s / 15, p = s % 15;
        mp[c * 15 + p] = fmaxf(y[c * 30 + 2 * p], y[c * 30 + 2 * p + 1]);
    }
    __syncthreads();
    for (int s = t; s < 352; s += 128) {
        int o = s / 11, p = s % 11;
        float acc = bc2[o];
        for (int c = 0; c < 16; c++) {
#pragma unroll
            for (int kk = 0; kk < 5; kk++)
                acc += Wc2[(o * 16 + c) * 5 + kk] * mp[c * 15 + p + kk];
        }
        dd[o * 11 + p] = fmaxf(acc, 0.f);
    }
    __syncthreads();
    {
        float acc = bh[t];
        for (int d = 0; d < 352; d++) acc += Wh[t * 352 + d] * dd[d];
        hh[t] = fmaxf(acc, 0.f);
    }
    __syncthreads();
    if (t < 10) {
        float acc = bo[t];
        for (int j = 0; j < 128; j++) acc += Wo[t * 128 + j] * hh[j];
        lg[t] = acc;
    }
    __syncthreads();
    if (t == 0) {
        float m = lg[0];
        for (int i = 1; i < 10; i++) m = fmaxf(m, lg[i]);
        float s = 0.f;
        for (int i = 0; i < 10; i++) s += expf(lg[i] - m);
        lse = m + logf(s);
    }
    __syncthreads();
    if (t < 10) out[b * 10 + t] = lg[t] - lse;
}

// ---------------- launch: kernel launches ONLY ----------------
extern "C" void kernel_launch(void* const* d_in, const int* in_sizes, int n_in,
                              void* d_out, int out_size) {
    const float* node_feat = (const float*)d_in[0];
    const float* edge_feat = (const float*)d_in[1];
    const float* node_degs = (const float*)d_in[2];
    const float* W0 = (const float*)d_in[3];
    const float* b0 = (const float*)d_in[4];
    const float* W1 = (const float*)d_in[5];
    const float* b1 = (const float*)d_in[6];
    const float* W2 = (const float*)d_in[7];
    const float* b2 = (const float*)d_in[8];
    const float* W3 = (const float*)d_in[9];
    const float* b3 = (const float*)d_in[10];
    const float* Wc1 = (const float*)d_in[11];
    const float* bc1 = (const float*)d_in[12];
    const float* Wc2 = (const float*)d_in[13];
    const float* bc2 = (const float*)d_in[14];
    const float* Wh = (const float*)d_in[15];
    const float* bh = (const float*)d_in[16];
    const float* Wo = (const float*)d_in[17];
    const float* bo = (const float*)d_in[18];
    const int* edge_row = (const int*)d_in[19];
    const int* edge_col = (const int*)d_in[20];
    float* out = (float*)d_out;

    // index: 0        1       2      3 <- ncu capture window (k_e2n)
    k_scanA<<<128, 1024>>>(node_degs);
    k_scanB<<<128, 1024>>>();
    k_fill<<<EE / 256, 256>>>(edge_row, edge_col);
    k_e2n<<<NN / 8, 256>>>(edge_feat, node_degs);
    k_z0g<<<NN / 64, 256>>>(node_feat, W0);

    k_layer<0><<<NN / 64, 256>>>(b0, node_degs, W1);
    k_layer<1><<<NN / 64, 256>>>(b1, node_degs, W2);
    k_layer<2><<<NN / 64, 256>>>(b2, node_degs, W3);
    k_layer3<<<NN / 8, 256>>>(node_degs, b3);

    k_topk<<<BB, 256>>>();
    k_classify<<<BB, 128>>>(Wc1, bc1, Wc2, bc2, Wh, bh, Wo, bo, out);
}

// round 15
// speedup vs baseline: 1.1274x; 1.1274x over previous
#include <cuda_runtime.h>
#include <math.h>

#define NN 131072          // nodes
#define EE 2097152         // edges
#define BB 64              // graphs
#define NPG 2048
#define KTOP 30
#define FULLMASK 0xffffffffu

// fast tanh: 1 - 2/(e^{2x}+1).  rel-err ~1e-6, inside the 1e-3 budget.
__device__ __forceinline__ float ftanh(float x) {
    float e = __expf(2.0f * x);
    return 1.0f - __fdividef(2.0f, e + 1.0f);
}

// ---------------- scratch (static device globals; no allocation) ----------------
__device__ int   g_rowstart[NN];
__device__ int   g_cursor[NN];
__device__ int   g_blocksums[128];
__device__ int2  g_csr[EE];        // .x = col, .y = eid
__device__ float g_z[NN * 32];
__device__ float g_z2[NN * 32];
__device__ float g_h0[NN * 32];
__device__ float g_h1[NN * 32];
__device__ float g_h2[NN * 32];
__device__ float g_z3[NN];
__device__ float g_h3[NN];
__device__ int   g_topk[BB * KTOP];

// ---------------- CSR build: prefix scan of degrees (2 kernels) ----------------
__global__ void k_scanA(const float* __restrict__ degs) {
    __shared__ int tmp[1024];
    int t = threadIdx.x;
    int idx = blockIdx.x * 1024 + t;
    int c = (int)(degs[idx] + 0.5f) - 1;             // node_degs = count + 1
    tmp[t] = c;
    __syncthreads();
    for (int off = 1; off < 1024; off <<= 1) {
        int v = (t >= off) ? tmp[t - off] : 0;
        __syncthreads();
        tmp[t] += v;
        __syncthreads();
    }
    g_rowstart[idx] = tmp[t] - c;                    // exclusive within block
    if (t == 1023) g_blocksums[blockIdx.x] = tmp[t];
}

__global__ void k_scanB() {
    __shared__ int bs[128];
    int t = threadIdx.x;
    if (t < 128) bs[t] = g_blocksums[t];
    __syncthreads();
    int off = 0;
    for (int i = 0; i < blockIdx.x; i++) off += bs[i];
    int idx = blockIdx.x * 1024 + t;
    int v = g_rowstart[idx] + off;
    g_rowstart[idx] = v;
    g_cursor[idx]   = v;
}

__global__ void k_fill(const int* __restrict__ erow, const int* __restrict__ ecol) {
    int e = blockIdx.x * 256 + threadIdx.x;
    int r = erow[e];
    int p = atomicAdd(&g_cursor[r], 1);
    g_csr[p] = make_int2(ecol[e], e);
}

// Predicated 8-wide gather group: no serial tail, all valid loads batched.
#define GATHER8(SRC, IDXEXPR, A)                                      \
    for (int k = 0; k < m; k += 8) {                                  \
        int e0 = __shfl_sync(FULLMASK, IDXEXPR, k);                   \
        int e1 = __shfl_sync(FULLMASK, IDXEXPR, k + 1);               \
        int e2 = __shfl_sync(FULLMASK, IDXEXPR, k + 2);               \
        int e3 = __shfl_sync(FULLMASK, IDXEXPR, k + 3);               \
        int e4 = __shfl_sync(FULLMASK, IDXEXPR, k + 4);               \
        int e5 = __shfl_sync(FULLMASK, IDXEXPR, k + 5);               \
        int e6 = __shfl_sync(FULLMASK, IDXEXPR, k + 6);               \
        int e7 = __shfl_sync(FULLMASK, IDXEXPR, k + 7);               \
        A##0 += SRC[e0 * 32 + lane];                                  \
        if (k + 1 < m) A##1 += SRC[e1 * 32 + lane];                   \
        if (k + 2 < m) A##2 += SRC[e2 * 32 + lane];                   \
        if (k + 3 < m) A##3 += SRC[e3 * 32 + lane];                   \
        if (k + 4 < m) A##4 += SRC[e4 * 32 + lane];                   \
        if (k + 5 < m) A##5 += SRC[e5 * 32 + lane];                   \
        if (k + 6 < m) A##6 += SRC[e6 * 32 + lane];                   \
        if (k + 7 < m) A##7 += SRC[e7 * 32 + lane];                   \
    }

// ---------------- z0: fused e2n gather + register-tiled GEMM ------------------
__global__ void k_z0(const float* __restrict__ nodef, const float* __restrict__ edgef,
                     const float* __restrict__ degs, const float* __restrict__ W0) {
    __shared__ float sWt[32 * 164];                  // [c][i], row pad 164
    __shared__ float se2n[64 * 32];                  // [nloc][ch]
    int t = threadIdx.x;
    int wid = t >> 5, lane = t & 31;
    int nbase = blockIdx.x * 64;

    for (int s = t; s < 32 * 160; s += 256) {
        int c = s / 160, i = s % 160;
        sWt[c * 164 + i] = W0[c * 160 + i];
    }

    // Phase A: e2n gather, warp-per-node, 8 rounds -> 64 nodes
    for (int rep = 0; rep < 8; rep++) {
        int nloc = rep * 8 + wid;
        int v = nbase + nloc;
        int cnt = (int)(degs[v] + 0.5f) - 1;
        int start = g_rowstart[v];
        float a0 = 0.f, a1 = 0.f, a2 = 0.f, a3 = 0.f;
        float a4 = 0.f, a5 = 0.f, a6 = 0.f, a7 = 0.f;
        for (int kb = 0; kb < cnt; kb += 32) {
            int m = min(32, cnt - kb);
            int eid = (lane < m) ? g_csr[start + kb + lane].y : 0;
            GATHER8(edgef, eid, a)
        }
        se2n[nloc * 32 + lane] =
            ((a0 + a1) + (a2 + a3)) + ((a4 + a5) + (a6 + a7));
    }
    __syncthreads();

    // Phase B: z = W0 @ [nf | e2n], warp computes 8 nodes x 32 ch
    float acc[8];
#pragma unroll
    for (int n = 0; n < 8; n++) acc[n] = 0.f;
    int n0 = wid * 8;
    const float4* nf4 = reinterpret_cast<const float4*>(nodef + (nbase + n0) * 128);

    for (int i4 = 0; i4 < 32; i4++) {                 // nf part: i = 0..127
        float4 wv = *reinterpret_cast<const float4*>(&sWt[lane * 164 + i4 * 4]);
#pragma unroll
        for (int n = 0; n < 8; n++) {
            float4 hv = __ldg(&nf4[n * 32 + i4]);     // warp-uniform broadcast
            acc[n] += wv.x * hv.x + wv.y * hv.y + wv.z * hv.z + wv.w * hv.w;
        }
    }
#pragma unroll
    for (int i4 = 0; i4 < 8; i4++) {                  // e2n part: i = 128..159
        float4 wv = *reinterpret_cast<const float4*>(&sWt[lane * 164 + 128 + i4 * 4]);
#pragma unroll
        for (int n = 0; n < 8; n++) {
            float4 hv = *reinterpret_cast<const float4*>(&se2n[(n0 + n) * 32 + i4 * 4]);
            acc[n] += wv.x * hv.x + wv.y * hv.y + wv.z * hv.z + wv.w * hv.w;
        }
    }
#pragma unroll
    for (int n = 0; n < 8; n++)
        g_z[(nbase + n0 + n) * 32 + lane] = acc[n];
}

// ---------------- GNN layer: register-tiled --------------
template <int STAGE>
__global__ void k_layer(const float* __restrict__ bias, const float* __restrict__ degs,
                        const float* __restrict__ Wn) {
    const float* zin  = (STAGE == 1) ? g_z2 : g_z;
    float* hout = (STAGE == 0) ? g_h0 : (STAGE == 1) ? g_h1 : g_h2;

    __shared__ float sWt[32 * 36];                   // [c][j], pad 36 (=4 mod 32)
    __shared__ float sh[64 * 32];                    // h tile
    int t = threadIdx.x;
    int wid = t >> 5, lane = t & 31;
    int nbase = blockIdx.x * 64;

    if (STAGE < 2) {
        for (int s = t; s < 1024; s += 256) {
            int c = s >> 5, j = s & 31;
            sWt[c * 36 + j] = Wn[c * 32 + j];
        }
    }
    float bl = bias[lane];

    // Phase A: gather pooled, tanh, stash h
    for (int rep = 0; rep < 8; rep++) {
        int nloc = rep * 8 + wid;
        int v = nbase + nloc;
        float deg = degs[v];
        int cnt = (int)(deg + 0.5f) - 1;
        int start = g_rowstart[v];

        float p0 = zin[v * 32 + lane], p1 = 0.f, p2 = 0.f, p3 = 0.f;
        float p4 = 0.f, p5 = 0.f, p6 = 0.f, p7 = 0.f;
        for (int kb = 0; kb < cnt; kb += 32) {
            int m = min(32, cnt - kb);
            int col = (lane < m) ? g_csr[start + kb + lane].x : 0;
            GATHER8(zin, col, p)
        }
        float p = ((p0 + p1) + (p2 + p3)) + ((p4 + p5) + (p6 + p7));
        float h = ftanh(__fdividef(p + bl, deg));
        sh[nloc * 32 + lane] = h;
        hout[v * 32 + lane] = h;
    }
    __syncthreads();

    // Phase B: projection
    int n0 = wid * 8;
    if (STAGE < 2) {
        float acc[8];
#pragma unroll
        for (int n = 0; n < 8; n++) acc[n] = 0.f;
#pragma unroll
        for (int i4 = 0; i4 < 8; i4++) {
            float4 wv = *reinterpret_cast<const float4*>(&sWt[lane * 36 + i4 * 4]);
#pragma unroll
            for (int n = 0; n < 8; n++) {
                float4 hv = *reinterpret_cast<const float4*>(&sh[(n0 + n) * 32 + i4 * 4]);
                acc[n] += wv.x * hv.x + wv.y * hv.y + wv.z * hv.z + wv.w * hv.w;
            }
        }
        float* zout = (STAGE == 0) ? g_z2 : g_z;
#pragma unroll
        for (int n = 0; n < 8; n++)
            zout[(nbase + n0 + n) * 32 + lane] = acc[n];
    } else {
        float w3 = Wn[lane];                          // 1x32, L2/const cached
#pragma unroll
        for (int n = 0; n < 8; n++) {
            float part = w3 * sh[(n0 + n) * 32 + lane];
#pragma unroll
            for (int o = 16; o; o >>= 1) part += __shfl_xor_sync(FULLMASK, part, o);
            if (lane == 0) g_z3[nbase + n0 + n] = part;
        }
    }
}

// ---------------- layer 3 (scalar channel) ----------------
__global__ void k_layer3(const float* __restrict__ degs, const float* __restrict__ b3) {
    int t = threadIdx.x;
    int warp = (blockIdx.x * 256 + t) >> 5;
    int lane = t & 31;
    int v = warp;
    float deg = degs[v];
    int cnt = (int)(deg + 0.5f) - 1;
    int start = g_rowstart[v];
    float s = 0.f;
    for (int k = lane; k < cnt; k += 32) s += g_z3[g_csr[start + k].x];
#pragma unroll
    for (int o = 16; o; o >>= 1) s += __shfl_xor_sync(FULLMASK, s, o);
    if (lane == 0) {
        float pooled = s + g_z3[v];
        g_h3[v] = ftanh(__fdividef(pooled + b3[0], deg));
    }
}

// ---------------- sortpool: top-K per graph by h3, JAX tie semantics ----------------
__global__ void k_topk() {
    int b = blockIdx.x;
    int t = threadIdx.x;                       // 256 threads
    __shared__ float sv[NPG];
    __shared__ float rv[256];
    __shared__ int   ri[256];
    for (int i = t; i < NPG; i += 256) sv[i] = g_h3[b * NPG + i];
    __syncthreads();
    for (int r = 0; r < KTOP; r++) {
        float bv = -3.0f;
        int bi = NPG;
        for (int i = t; i < NPG; i += 256) {
            float v = sv[i];
            if (v > bv || (v == bv && i < bi)) { bv = v; bi = i; }
        }
        rv[t] = bv; ri[t] = bi;
        __syncthreads();
        for (int o = 128; o > 0; o >>= 1) {
            if (t < o) {
                float v2 = rv[t + o]; int i2 = ri[t + o];
                if (v2 > rv[t] || (v2 == rv[t] && i2 < ri[t])) { rv[t] = v2; ri[t] = i2; }
            }
            __syncthreads();
        }
        if (t == 0) { g_topk[b * KTOP + r] = ri[0]; sv[ri[0]] = -2.0f; }
        __syncthreads();
    }
}

// ---------------- CNN head + MLP + log_softmax, one block per graph ----------------
__global__ void k_classify(const float* __restrict__ Wc1, const float* __restrict__ bc1,
                           const float* __restrict__ Wc2, const float* __restrict__ bc2,
                           const float* __restrict__ Wh,  const float* __restrict__ bh,
                           const float* __restrict__ Wo,  const float* __restrict__ bo,
                           float* __restrict__ out) {
    int b = blockIdx.x, t = threadIdx.x;       // 128 threads
    __shared__ float pg[KTOP * 97];
    __shared__ float y[16 * 30];
    __shared__ float mp[16 * 15];
    __shared__ float dd[352];
    __shared__ float hh[128];
    __shared__ float lg[10];
    __shared__ float lse;

    for (int s = t; s < KTOP * 97; s += 128) {
        int k = s / 97, d = s % 97;
        int node = g_topk[b * KTOP + k] + b * NPG;
        float v;
        if (d < 32)      v = g_h0[node * 32 + d];
        else if (d < 64) v = g_h1[node * 32 + (d - 32)];
        else if (d < 96) v = g_h2[node * 32 + (d - 64)];
        else             v = g_h3[node];
        pg[k * 97 + d] = v;
    }
    __syncthreads();
    for (int s = t; s < 480; s += 128) {
        int c = s / 30, k = s % 30;
        float acc = bc1[c];
        for (int d = 0; d < 97; d++) acc += Wc1[c * 97 + d] * pg[k * 97 + d];
        y[c * 30 + k] = fmaxf(acc, 0.f);
    }
    __syncthreads();
    for (int s = t; s < 240; s += 128) {
        int c = s / 15, p = s % 15;
        mp[c * 15 + p] = fmaxf(y[c * 30 + 2 * p], y[c * 30 + 2 * p + 1]);
    }
    __syncthreads();
    for (int s = t; s < 352; s += 128) {
        int o = s / 11, p = s % 11;
        float acc = bc2[o];
        for (int c = 0; c < 16; c++) {
#pragma unroll
            for (int kk = 0; kk < 5; kk++)
                acc += Wc2[(o * 16 + c) * 5 + kk] * mp[c * 15 + p + kk];
        }
        dd[o * 11 + p] = fmaxf(acc, 0.f);
    }
    __syncthreads();
    {
        float acc = bh[t];
        for (int d = 0; d < 352; d++) acc += Wh[t * 352 + d] * dd[d];
        hh[t] = fmaxf(acc, 0.f);
    }
    __syncthreads();
    if (t < 10) {
        float acc = bo[t];
        for (int j = 0; j < 128; j++) acc += Wo[t * 128 + j] * hh[j];
        lg[t] = acc;
    }
    __syncthreads();
    if (t == 0) {
        float m = lg[0];
        for (int i = 1; i < 10; i++) m = fmaxf(m, lg[i]);
        float s = 0.f;
        for (int i = 0; i < 10; i++) s += expf(lg[i] - m);
        lse = m + logf(s);
    }
    __syncthreads();
    if (t < 10) out[b * 10 + t] = lg[t] - lse;
}

// ---------------- launch: kernel launches ONLY ----------------
extern "C" void kernel_launch(void* const* d_in, const int* in_sizes, int n_in,
                              void* d_out, int out_size) {
    const float* node_feat = (const float*)d_in[0];
    const float* edge_feat = (const float*)d_in[1];
    const float* node_degs = (const float*)d_in[2];
    const float* W0 = (const float*)d_in[3];
    const float* b0 = (const float*)d_in[4];
    const float* W1 = (const float*)d_in[5];
    const float* b1 = (const float*)d_in[6];
    const float* W2 = (const float*)d_in[7];
    const float* b2 = (const float*)d_in[8];
    const float* W3 = (const float*)d_in[9];
    const float* b3 = (const float*)d_in[10];
    const float* Wc1 = (const float*)d_in[11];
    const float* bc1 = (const float*)d_in[12];
    const float* Wc2 = (const float*)d_in[13];
    const float* bc2 = (const float*)d_in[14];
    const float* Wh = (const float*)d_in[15];
    const float* bh = (const float*)d_in[16];
    const float* Wo = (const float*)d_in[17];
    const float* bo = (const float*)d_in[18];
    const int* edge_row = (const int*)d_in[19];
    const int* edge_col = (const int*)d_in[20];
    float* out = (float*)d_out;

    // index: 0        1       2      3 <- ncu capture window (k_z0)
    k_scanA<<<128, 1024>>>(node_degs);
    k_scanB<<<128, 1024>>>();
    k_fill<<<EE / 256, 256>>>(edge_row, edge_col);
    k_z0<<<NN / 64, 256>>>(node_feat, edge_feat, node_degs, W0);

    k_layer<0><<<NN / 64, 256>>>(b0, node_degs, W1);
    k_layer<1><<<NN / 64, 256>>>(b1, node_degs, W2);
    k_layer<2><<<NN / 64, 256>>>(b2, node_degs, W3);
    k_layer3<<<NN / 8, 256>>>(node_degs, b3);

    k_topk<<<BB, 256>>>();
    k_classify<<<BB, 128>>>(Wc1, bc1, Wc2, bc2, Wh, bh, Wo, bo, out);
}